// round 15
// baseline (speedup 1.0000x reference)
#include <cuda_runtime.h>
#include <cuda_fp16.h>

#define BSZ 4
#define SEQ 256
#define DIM 128
#define HID 128
#define DFF 512
#define MROWS (BSZ*SEQ)   // 1024
#define LGSZ (BSZ*SEQ*SEQ)

// ---------------- scratch (device globals; no allocations) ----------------
__device__ float g_Wbig1[DIM*384];    // [Ww1@W1q | Ww1@W1k | Ww1@Wd1]
__device__ float g_Wbig2[DIM*384];
__device__ float g_bbig1[384];        // [bw1@W1q+b1 | bw1@W1k | bw1@Wd1]
__device__ float g_bbig2[384];
__device__ float g_buf1[MROWS*384];   // [T1A | T1B | VW1]
__device__ float g_buf2[MROWS*384];   // [TkA | TkB | VW2]
__device__ float g_Tq  [MROWS*256];   // [TqA | TqB]
__device__ __half g_lg [4*LGSZ];      // sim partials (4 H-quarters), fp16
__device__ __half g_lgT[4*LGSZ];      // transposed partials (self-attn only)
__device__ float g_o1 [MROWS*DIM];
__device__ float g_o2 [MROWS*DIM];

// ---------------- prep: Wbig tiles (y<4) + bbig (y==4), both sets (z) ------
__global__ void prep_kernel(const float* __restrict__ Ww1, const float* __restrict__ Ww2,
                            const float* __restrict__ W1q, const float* __restrict__ W1k,
                            const float* __restrict__ Wd1, const float* __restrict__ Wd2,
                            const float* __restrict__ bw1, const float* __restrict__ bw2,
                            const float* __restrict__ b1,
                            float* __restrict__ Wbig1, float* __restrict__ Wbig2,
                            float* __restrict__ bbig1, float* __restrict__ bbig2)
{
    const float* Ww = blockIdx.z ? Ww2 : Ww1;
    const float* Wd = blockIdx.z ? Wd2 : Wd1;
    const float* bw = blockIdx.z ? bw2 : bw1;
    float* Wbig = blockIdx.z ? Wbig2 : Wbig1;
    float* bbig = blockIdx.z ? bbig2 : bbig1;
    int n0p = blockIdx.x * 32;             // 0..352
    int grp = n0p >> 7;                    // 0:W1q 1:W1k 2:Wd
    const float* Bsrc = ((grp == 0) ? W1q : (grp == 1) ? W1k : Wd) + (n0p & 127);
    int tid = threadIdx.x;

    if (blockIdx.y == 4) {                 // bias row: bbig[n0p .. n0p+32)
        int w = tid >> 5, lane = tid & 31;
        for (int c = w; c < 32; c += 8) {
            int np = n0p + c;
            float s = 0.f;
            #pragma unroll
            for (int i = 0; i < 4; i++) {
                int k = lane + 32 * i;
                s += bw[k] * Bsrc[k * 128 + c];
            }
            #pragma unroll
            for (int o = 16; o; o >>= 1) s += __shfl_xor_sync(0xffffffffu, s, o);
            if (lane == 0) {
                if (grp == 0) s += b1[np & 127];
                bbig[np] = s;
            }
        }
        return;
    }

    int m0 = blockIdx.y * 32;
    __shared__ float As[32][34], Bs[32][34];
    int tx = tid & 15, ty = tid >> 4;
    float a00 = 0.f, a01 = 0.f, a10 = 0.f, a11 = 0.f;
    for (int k0 = 0; k0 < 128; k0 += 32) {
        #pragma unroll
        for (int i = 0; i < 4; i++) {
            int idx = tid + i * 256;
            int ka = idx & 31, ma = idx >> 5;
            As[ka][ma] = Ww[(m0 + ma) * 128 + k0 + ka];
            int nb = idx & 31, kb = idx >> 5;
            Bs[kb][nb] = Bsrc[(k0 + kb) * 128 + nb];
        }
        __syncthreads();
        #pragma unroll
        for (int kk = 0; kk < 32; kk++) {
            float2 a = *(const float2*)&As[kk][ty * 2];
            float2 b = *(const float2*)&Bs[kk][tx * 2];
            a00 += a.x * b.x; a01 += a.x * b.y;
            a10 += a.y * b.x; a11 += a.y * b.y;
        }
        __syncthreads();
    }
    int m = m0 + ty * 2, n = n0p + tx * 2;
    Wbig[m * 384 + n]           = a00;
    Wbig[m * 384 + n + 1]       = a01;
    Wbig[(m + 1) * 384 + n]     = a10;
    Wbig[(m + 1) * 384 + n + 1] = a11;
}

// ---------------- SGEMM 32x64 tile, 256 thr, 2x4 micro ---------------------
__global__ void sgemm2x4_kernel(const float* __restrict__ A0, const float* __restrict__ B0,
                                const float* __restrict__ bias0, float* __restrict__ C0,
                                const float* __restrict__ A1, const float* __restrict__ B1,
                                const float* __restrict__ bias1, float* __restrict__ C1,
                                int K, int lda, int ldb, int ldc, int relu)
{
    __shared__ float As[32][34];
    __shared__ float Bs[32][68];
    int z = blockIdx.z;
    bool use1 = (z == 1) && (C1 != 0);
    const float* A = use1 ? A1 : A0;
    const float* B = use1 ? B1 : B0;
    const float* bias = use1 ? bias1 : bias0;
    float* C = use1 ? C1 : C0;
    int m0 = blockIdx.y * 32, n0 = blockIdx.x * 64;
    int tid = threadIdx.x;
    int tx = tid & 15, ty = tid >> 4;
    float acc[2][4] = {};

    for (int k0 = 0; k0 < K; k0 += 32) {
        #pragma unroll
        for (int i = 0; i < 4; i++) {
            int idx = tid + i * 256;
            int ka = idx & 31, ma = idx >> 5;
            As[ka][ma] = A[(long)(m0 + ma) * lda + k0 + ka];
        }
        #pragma unroll
        for (int i = 0; i < 8; i++) {
            int idx = tid + i * 256;
            int nb = idx & 63, kb = idx >> 6;
            Bs[kb][nb] = B[(long)(k0 + kb) * ldb + n0 + nb];
        }
        __syncthreads();
        #pragma unroll
        for (int kk = 0; kk < 32; kk++) {
            float2 a = *(const float2*)&As[kk][ty * 2];
            float4 b = *(const float4*)&Bs[kk][tx * 4];
            float bv[4] = {b.x, b.y, b.z, b.w};
            #pragma unroll
            for (int j = 0; j < 4; j++) {
                acc[0][j] += a.x * bv[j];
                acc[1][j] += a.y * bv[j];
            }
        }
        __syncthreads();
    }
    int m = m0 + ty * 2, n = n0 + tx * 4;
    float bb[4] = {0.f, 0.f, 0.f, 0.f};
    if (bias) {
        #pragma unroll
        for (int j = 0; j < 4; j++) bb[j] = bias[n + j];
    }
    #pragma unroll
    for (int i = 0; i < 2; i++) {
        float4 o4;
        float v0 = acc[i][0] + bb[0], v1 = acc[i][1] + bb[1];
        float v2 = acc[i][2] + bb[2], v3 = acc[i][3] + bb[3];
        if (relu) { v0=fmaxf(v0,0.f); v1=fmaxf(v1,0.f); v2=fmaxf(v2,0.f); v3=fmaxf(v3,0.f); }
        o4.x=v0; o4.y=v1; o4.z=v2; o4.w=v3;
        *(float4*)&C[(long)(m + i) * ldc + n] = o4;
    }
}

// ---------------- pairwise similarity; fp16 logit partials -----------------
__global__ void sim_kernel(const float* __restrict__ qbase, int ldq,
                           const float* __restrict__ kbase, int ldk,
                           const float* __restrict__ W2,
                           __half* __restrict__ lg, __half* __restrict__ lgT, int dual)
{
    __shared__ float sqa[32][34];
    __shared__ float sqb[32][34];
    __shared__ float skb[32][68];
    __shared__ float ska[32][68];
    __shared__ float sw[32];

    int z = blockIdx.z, b = z >> 2, hq = z & 3;
    int h0 = hq * 32;
    int q0 = blockIdx.y * 32, k0 = blockIdx.x * 64;
    const float* qp = qbase + (long)(b * SEQ + q0) * ldq;
    const float* kp = kbase + (long)(b * SEQ + k0) * ldk;
    int tid = threadIdx.x;
    int tx = tid & 15, ty = tid >> 4;
    float acc[2][4] = {};

    #pragma unroll
    for (int i = 0; i < 4; i++) {
        int idx = tid + i * 256;
        int r = idx >> 5, h = idx & 31;
        sqa[h][r] = qp[(long)r * ldq + h0 + h];
        if (dual) sqb[h][r] = qp[(long)r * ldq + 128 + h0 + h];
    }
    #pragma unroll
    for (int i = 0; i < 8; i++) {
        int idx = tid + i * 256;
        int r = idx >> 5, h = idx & 31;
        skb[h][r] = kp[(long)r * ldk + 128 + h0 + h];
        if (dual) ska[h][r] = kp[(long)r * ldk + h0 + h];
    }
    if (tid < 32) sw[tid] = W2[h0 + tid];
    __syncthreads();

    #pragma unroll 4
    for (int h = 0; h < 32; h++) {
        float w = sw[h];
        float2 a1r = *(const float2*)&sqa[h][ty * 2];
        float4 b1r = *(const float4*)&skb[h][tx * 4];
        float a1v[2] = {a1r.x, a1r.y};
        float b1v[4] = {b1r.x, b1r.y, b1r.z, b1r.w};
        #pragma unroll
        for (int i = 0; i < 2; i++)
            #pragma unroll
            for (int j = 0; j < 4; j++)
                acc[i][j] += fmaxf(a1v[i] + b1v[j], 0.f) * w;
        if (dual) {
            float2 qb = *(const float2*)&sqb[h][ty * 2];
            float4 ka = *(const float4*)&ska[h][tx * 4];
            float qv[2] = {qb.x, qb.y};
            float kv[4] = {ka.x, ka.y, ka.z, ka.w};
            #pragma unroll
            for (int i = 0; i < 2; i++)
                #pragma unroll
                for (int j = 0; j < 4; j++)
                    acc[i][j] += fmaxf(kv[j] + qv[i], 0.f) * w;
        }
    }

    __half* outp = lg + (long)hq * LGSZ;
    #pragma unroll
    for (int i = 0; i < 2; i++) {
        int q = q0 + ty * 2 + i;
        __half2 h01 = __floats2half2_rn(acc[i][0], acc[i][1]);
        __half2 h23 = __floats2half2_rn(acc[i][2], acc[i][3]);
        uint2 u;
        u.x = *(unsigned int*)&h01;
        u.y = *(unsigned int*)&h23;
        *(uint2*)&outp[((long)b * SEQ + q) * SEQ + k0 + tx * 4] = u;
    }

    if (!dual) {
        // transpose tile through smem (reuse skb: 32*68=2176 >= 64*33=2112)
        __syncthreads();
        float* st = &skb[0][0];
        #pragma unroll
        for (int i = 0; i < 2; i++) {
            int ql = ty * 2 + i;
            #pragma unroll
            for (int j = 0; j < 4; j++) {
                int kl = tx * 4 + j;
                st[kl * 33 + ql] = acc[i][j];
            }
        }
        __syncthreads();
        __half* outT = lgT + (long)hq * LGSZ;
        #pragma unroll
        for (int i = 0; i < 8; i++) {
            int idx = tid + i * 256;
            int r = idx >> 5, c = idx & 31;
            outT[((long)b * SEQ + k0 + r) * SEQ + q0 + c] = __float2half(st[r * 33 + c]);
        }
    }
}

// ---------------- fused softmax + (probs @ VW) + bias + residual + LN ------
// (R14-proven; dead placeholder stores removed)
__global__ void attn_ln_kernel(const __half* __restrict__ lg, const __half* __restrict__ lgT,
                               const float* __restrict__ mask, const float* __restrict__ b2p,
                               const float* __restrict__ VW, int ldvw,
                               const float* __restrict__ bias, const float* __restrict__ res,
                               const float* __restrict__ g, const float* __restrict__ be,
                               float* __restrict__ out, int sym)
{
    __shared__ float sprob[8][264];
    __shared__ float Bs[2][32][132];
    __shared__ float sacc[2][8][128];
    __shared__ float red[8][2][2];
    int m0 = blockIdx.x * 8;
    int b = m0 >> 8;
    int tid = threadIdx.x;
    int w = tid >> 5, lane = tid & 31;
    float c2 = 2.f * b2p[0];

    // ---- phase 1: softmax; warp pair per row ----
    {
        int r8 = w >> 1, hf = w & 1;
        int q = m0 + r8;
        long base4 = (long)q * SEQ + hf * 128 + lane * 4;
        float xs0 = 0.f, xs1 = 0.f, xs2 = 0.f, xs3 = 0.f;
        #pragma unroll
        for (int p = 0; p < 4; p++) {
            uint2 u = *(const uint2*)&lg[(long)p * LGSZ + base4];
            float2 f0 = __half22float2(*(__half2*)&u.x);
            float2 f1 = __half22float2(*(__half2*)&u.y);
            xs0 += f0.x; xs1 += f0.y; xs2 += f1.x; xs3 += f1.y;
        }
        if (sym) {
            #pragma unroll
            for (int p = 0; p < 4; p++) {
                uint2 u = *(const uint2*)&lgT[(long)p * LGSZ + base4];
                float2 f0 = __half22float2(*(__half2*)&u.x);
                float2 f1 = __half22float2(*(__half2*)&u.y);
                xs0 += f0.x; xs1 += f0.y; xs2 += f1.x; xs3 += f1.y;
            }
        }
        float4 mk = *(const float4*)&mask[base4];
        float xv[4];
        xv[0] = xs0 + c2 + mk.x * (-1e9f);
        xv[1] = xs1 + c2 + mk.y * (-1e9f);
        xv[2] = xs2 + c2 + mk.z * (-1e9f);
        xv[3] = xs3 + c2 + mk.w * (-1e9f);

        float mx = fmaxf(fmaxf(xv[0], xv[1]), fmaxf(xv[2], xv[3]));
        #pragma unroll
        for (int o = 16; o; o >>= 1) mx = fmaxf(mx, __shfl_xor_sync(0xffffffffu, mx, o));
        if (lane == 0) red[r8][hf][0] = mx;
        __syncthreads();
        float gmx = fmaxf(red[r8][0][0], red[r8][1][0]);
        float e0 = __expf(xv[0] - gmx), e1 = __expf(xv[1] - gmx);
        float e2 = __expf(xv[2] - gmx), e3 = __expf(xv[3] - gmx);
        float ssum = e0 + e1 + e2 + e3;
        float4 ev = {e0, e1, e2, e3};
        *(float4*)&sprob[r8][hf * 128 + lane * 4] = ev;
        #pragma unroll
        for (int o = 16; o; o >>= 1) ssum += __shfl_xor_sync(0xffffffffu, ssum, o);
        if (lane == 0) red[r8][hf][1] = ssum;
    }

    // ---- phase 2: warp = (kh, rq, cg): rows rq*4..+3, col cg*32+lane ----
    int kh = w >> 3, sub = w & 7;
    int rq = sub >> 2, cg = sub & 3;
    int n = cg * 32 + lane;
    float acc[4] = {};

    #pragma unroll
    for (int it = 0; it < 4; it++) {
        __syncthreads();
        #pragma unroll
        for (int j = 0; j < 2; j++) {
            int idx = tid + j * 512;
            int n4 = idx & 31, kb = idx >> 5;
            *(float4*)&Bs[0][kb][n4 * 4] =
                *(const float4*)&VW[(long)(b * SEQ + it * 32 + kb) * ldvw + n4 * 4];
            *(float4*)&Bs[1][kb][n4 * 4] =
                *(const float4*)&VW[(long)(b * SEQ + 128 + it * 32 + kb) * ldvw + n4 * 4];
        }
        __syncthreads();
        int kbase = kh * 128 + it * 32;
        #pragma unroll
        for (int kk = 0; kk < 32; kk++) {
            float bv = Bs[kh][kk][n];
            #pragma unroll
            for (int j = 0; j < 4; j++)
                acc[j] += sprob[rq * 4 + j][kbase + kk] * bv;
        }
    }

    #pragma unroll
    for (int j = 0; j < 4; j++)
        sacc[kh][rq * 4 + j][n] = acc[j];
    __syncthreads();

    // ---- epilogue: warp per row (tid < 256), 4 cols per lane, LN ----------
    if (tid < 256) {
        int r = tid >> 5;
        int q = m0 + r;
        float inv = 1.f / (red[r][0][1] + red[r][1][1]);
        float v[4];
        #pragma unroll
        for (int c = 0; c < 4; c++) {
            int nn = lane * 4 + c;
            v[c] = (sacc[0][r][nn] + sacc[1][r][nn]) * inv
                 + bias[nn] + res[(long)q * 128 + nn];
        }
        float s = v[0] + v[1] + v[2] + v[3];
        #pragma unroll
        for (int o = 16; o; o >>= 1) s += __shfl_xor_sync(0xffffffffu, s, o);
        float mean = s * (1.f / 128.f);
        float vs = 0.f;
        #pragma unroll
        for (int c = 0; c < 4; c++) { float d = v[c] - mean; vs += d * d; }
        #pragma unroll
        for (int o = 16; o; o >>= 1) vs += __shfl_xor_sync(0xffffffffu, vs, o);
        float invstd = rsqrtf(vs * (1.f / 128.f) + 1e-6f);
        #pragma unroll
        for (int c = 0; c < 4; c++) {
            int nn = lane * 4 + c;
            out[(long)q * 128 + nn] = (v[c] - mean) * invstd * g[nn] + be[nn];
        }
    }
}

// ---------------- fully fused FFN: LN(relu(A@Wf1+bf1)@Wf2+bf2+A) -----------
// 8 rows/block, 512 threads, grid 128. H kept entirely in smem.
__global__ void ffn_kernel(const float* __restrict__ A,
                           const float* __restrict__ Wf1, const float* __restrict__ bf1,
                           const float* __restrict__ Wf2, const float* __restrict__ bf2,
                           const float* __restrict__ g, const float* __restrict__ be,
                           float* __restrict__ out)
{
    __shared__ float sA[128][9];      // [k][r] o2 tile
    __shared__ float sB[32][132];     // weight chunk (shared by both phases)
    __shared__ float sH[8][520];      // hidden, relu'd
    __shared__ float red[8][2][2];
    int m0 = blockIdx.x * 8;
    int tid = threadIdx.x;

    // load A tile (8 rows x 128 cols) transposed into sA
    #pragma unroll
    for (int i = 0; i < 2; i++) {
        int idx = tid + i * 512;          // 0..1023
        int r = idx >> 7, k = idx & 127;
        sA[k][r] = A[(long)(m0 + r) * 128 + k];
    }

    // ---- phase A: H = relu(A @ Wf1 + bf1), j in 4 quarters of 128 ----
    int rA = tid >> 6, jc = tid & 63;      // row, col-pair index
    for (int jq = 0; jq < 4; jq++) {
        float acc0 = 0.f, acc1 = 0.f;
        for (int kc = 0; kc < 4; kc++) {
            __syncthreads();
            #pragma unroll
            for (int i = 0; i < 2; i++) {
                int idx = tid + i * 512;   // 1024 float4? 32x128=4096 floats=1024 f4
                int c4 = idx & 31, kr = idx >> 5;
                *(float4*)&sB[kr][c4 * 4] =
                    *(const float4*)&Wf1[(long)(kc * 32 + kr) * 512 + jq * 128 + c4 * 4];
            }
            __syncthreads();
            #pragma unroll
            for (int kk = 0; kk < 32; kk++) {
                float a = sA[kc * 32 + kk][rA];
                float2 bv = *(const float2*)&sB[kk][jc * 2];
                acc0 += a * bv.x;
                acc1 += a * bv.y;
            }
        }
        int j = jq * 128 + jc * 2;
        float2 bb = *(const float2*)&bf1[j];
        sH[rA][j]     = fmaxf(acc0 + bb.x, 0.f);
        sH[rA][j + 1] = fmaxf(acc1 + bb.y, 0.f);
    }

    // ---- phase B: out = LN(H @ Wf2 + bf2 + A_row) ----
    int w = tid >> 5, lane = tid & 31;
    int r8 = w >> 1, hf = w & 1;
    int q = m0 + r8;
    int n = hf * 64 + lane * 2;
    float acc0 = 0.f, acc1 = 0.f;
    for (int kc = 0; kc < 16; kc++) {
        __syncthreads();                 // first iter also guards sH completion
        #pragma unroll
        for (int i = 0; i < 2; i++) {
            int idx = tid + i * 512;
            int n4 = idx & 31, kr = idx >> 5;
            *(float4*)&sB[kr][n4 * 4] =
                *(const float4*)&Wf2[(long)(kc * 32 + kr) * 128 + n4 * 4];
        }
        __syncthreads();
        #pragma unroll
        for (int kk = 0; kk < 32; kk++) {
            float a = sH[r8][kc * 32 + kk];
            float2 bv = *(const float2*)&sB[kk][n];
            acc0 += a * bv.x;
            acc1 += a * bv.y;
        }
    }

    float v0 = acc0 + bf2[n]     + sA[n][r8];
    float v1 = acc1 + bf2[n + 1] + sA[n + 1][r8];
    float s = v0 + v1;
    #pragma unroll
    for (int o = 16; o; o >>= 1) s += __shfl_xor_sync(0xffffffffu, s, o);
    if (lane == 0) red[r8][hf][0] = s;
    __syncthreads();
    float mean = (red[r8][0][0] + red[r8][1][0]) * (1.f / 128.f);
    float d0 = v0 - mean, d1 = v1 - mean;
    float vs = d0 * d0 + d1 * d1;
    #pragma unroll
    for (int o = 16; o; o >>= 1) vs += __shfl_xor_sync(0xffffffffu, vs, o);
    if (lane == 0) red[r8][hf][1] = vs;
    __syncthreads();
    float invstd = rsqrtf((red[r8][0][1] + red[r8][1][1]) * (1.f / 128.f) + 1e-6f);
    out[(long)q * 128 + n]     = d0 * invstd * g[n]     + be[n];
    out[(long)q * 128 + n + 1] = d1 * invstd * g[n + 1] + be[n + 1];
}

// ---------------- host orchestration ----------------
extern "C" void kernel_launch(void* const* d_in, const int* in_sizes, int n_in,
                              void* d_out, int out_size)
{
    (void)in_sizes; (void)n_in; (void)out_size;
    const float* x    = (const float*)d_in[0];
    const float* enc  = (const float*)d_in[1];
    const float* cmsk = (const float*)d_in[2];
    const float* dmsk = (const float*)d_in[3];
    const float* W1q  = (const float*)d_in[4];
    const float* W1k  = (const float*)d_in[5];
    const float* b1   = (const float*)d_in[6];
    const float* W2   = (const float*)d_in[7];
    const float* b2   = (const float*)d_in[8];
    const float* Ww1  = (const float*)d_in[9];
    const float* bw1  = (const float*)d_in[10];
    const float* Wd1  = (const float*)d_in[11];
    const float* bd1  = (const float*)d_in[12];
    const float* Ww2  = (const float*)d_in[13];
    const float* bw2  = (const float*)d_in[14];
    const float* Wd2  = (const float*)d_in[15];
    const float* bd2  = (const float*)d_in[16];
    const float* Wf1  = (const float*)d_in[17];
    const float* bf1  = (const float*)d_in[18];
    const float* Wf2  = (const float*)d_in[19];
    const float* bf2  = (const float*)d_in[20];
    const float* ln1g = (const float*)d_in[21];
    const float* ln1b = (const float*)d_in[22];
    const float* ln2g = (const float*)d_in[23];
    const float* ln2b = (const float*)d_in[24];
    const float* ln3g = (const float*)d_in[25];
    const float* ln3b = (const float*)d_in[26];
    float* out = (float*)d_out;

    float *Wb1, *Wb2, *bb1, *bb2, *buf1, *buf2, *Tq, *o1, *o2;
    __half *lg, *lgT;
    cudaGetSymbolAddress((void**)&Wb1,   g_Wbig1);
    cudaGetSymbolAddress((void**)&Wb2,   g_Wbig2);
    cudaGetSymbolAddress((void**)&bb1,   g_bbig1);
    cudaGetSymbolAddress((void**)&bb2,   g_bbig2);
    cudaGetSymbolAddress((void**)&buf1,  g_buf1);
    cudaGetSymbolAddress((void**)&buf2,  g_buf2);
    cudaGetSymbolAddress((void**)&Tq,    g_Tq);
    cudaGetSymbolAddress((void**)&lg,    g_lg);
    cudaGetSymbolAddress((void**)&lgT,   g_lgT);
    cudaGetSymbolAddress((void**)&o1,    g_o1);
    cudaGetSymbolAddress((void**)&o2,    g_o2);

    dim3 simGrid(SEQ / 64, SEQ / 32, BSZ * 4);   // 512 blocks

    // ---- prep (weights only): Wbig tiles + bias row ----
    prep_kernel<<<dim3(12, 5, 2), 256>>>(Ww1, Ww2, W1q, W1k, Wd1, Wd2,
                                         bw1, bw2, b1, Wb1, Wb2, bb1, bb2);

    // ---- batched projection: buf = [TA | TB | VW] for x and enc ----
    sgemm2x4_kernel<<<dim3(6, 32, 2), 256>>>(x, Wb1, bb1, buf1,
                                             enc, Wb2, bb2, buf2,
                                             128, 128, 384, 384, 0);

    // ---- self-attention: logits = S + S^T (lgT written coalesced by sim) --
    sim_kernel<<<simGrid, 256>>>(buf1, 384, buf1, 384, W2, lg, lgT, 0);
    attn_ln_kernel<<<MROWS / 8, 512>>>(lg, lgT, cmsk, b2, buf1 + 256, 384,
                                       bd1, x, ln1g, ln1b, o1, 1);

    // ---- cross-attention ----
    sgemm2x4_kernel<<<dim3(4, 32, 1), 256>>>(o1, Wb2, bb2, Tq,
                                             0, 0, 0, 0,
                                             128, 128, 384, 256, 0);
    sim_kernel<<<simGrid, 256>>>(Tq, 256, buf2, 384, W2, lg, lgT, 1);
    attn_ln_kernel<<<MROWS / 8, 512>>>(lg, lgT, dmsk, b2, buf2 + 256, 384,
                                       bd2, o1, ln2g, ln2b, o2, 0);

    // ---- FFN: one fused kernel ----
    ffn_kernel<<<MROWS / 8, 512>>>(o2, Wf1, bf1, Wf2, bf2, ln3g, ln3b, out);
}

// round 16
// speedup vs baseline: 1.0756x; 1.0756x over previous
#include <cuda_runtime.h>
#include <cuda_fp16.h>

#define BSZ 4
#define SEQ 256
#define DIM 128
#define HID 128
#define DFF 512
#define MROWS (BSZ*SEQ)   // 1024
#define LGSZ (BSZ*SEQ*SEQ)

// ---------------- scratch (device globals; no allocations) ----------------
__device__ float g_Wbig1[DIM*384];    // [Ww1@W1q | Ww1@W1k | Ww1@Wd1]
__device__ float g_Wbig2[DIM*384];
__device__ float g_bbig1[384];        // [bw1@W1q+b1 | bw1@W1k | bw1@Wd1]
__device__ float g_bbig2[384];
__device__ float g_buf1[MROWS*384];   // [T1A | T1B | VW1]
__device__ float g_buf2[MROWS*384];   // [TkA | TkB | VW2]
__device__ float g_Tq  [MROWS*256];   // [TqA | TqB]
__device__ __half g_lg [4*LGSZ];      // sim partials (4 H-quarters), fp16
__device__ __half g_lgT[4*LGSZ];      // transposed partials (self-attn only)
__device__ float g_o1 [MROWS*DIM];
__device__ float g_o2 [MROWS*DIM];
__device__ __half g_fh [MROWS*DFF];   // FFN hidden, fp16

// ---------------- prep: Wbig tiles (y<4) + bbig (y==4), both sets (z) ------
__global__ void prep_kernel(const float* __restrict__ Ww1, const float* __restrict__ Ww2,
                            const float* __restrict__ W1q, const float* __restrict__ W1k,
                            const float* __restrict__ Wd1, const float* __restrict__ Wd2,
                            const float* __restrict__ bw1, const float* __restrict__ bw2,
                            const float* __restrict__ b1,
                            float* __restrict__ Wbig1, float* __restrict__ Wbig2,
                            float* __restrict__ bbig1, float* __restrict__ bbig2)
{
    const float* Ww = blockIdx.z ? Ww2 : Ww1;
    const float* Wd = blockIdx.z ? Wd2 : Wd1;
    const float* bw = blockIdx.z ? bw2 : bw1;
    float* Wbig = blockIdx.z ? Wbig2 : Wbig1;
    float* bbig = blockIdx.z ? bbig2 : bbig1;
    int n0p = blockIdx.x * 32;             // 0..352
    int grp = n0p >> 7;                    // 0:W1q 1:W1k 2:Wd
    const float* Bsrc = ((grp == 0) ? W1q : (grp == 1) ? W1k : Wd) + (n0p & 127);
    int tid = threadIdx.x;

    if (blockIdx.y == 4) {                 // bias row: bbig[n0p .. n0p+32)
        int w = tid >> 5, lane = tid & 31;
        for (int c = w; c < 32; c += 8) {
            int np = n0p + c;
            float s = 0.f;
            #pragma unroll
            for (int i = 0; i < 4; i++) {
                int k = lane + 32 * i;
                s += bw[k] * Bsrc[k * 128 + c];
            }
            #pragma unroll
            for (int o = 16; o; o >>= 1) s += __shfl_xor_sync(0xffffffffu, s, o);
            if (lane == 0) {
                if (grp == 0) s += b1[np & 127];
                bbig[np] = s;
            }
        }
        return;
    }

    int m0 = blockIdx.y * 32;
    __shared__ float As[32][34], Bs[32][34];
    int tx = tid & 15, ty = tid >> 4;
    float a00 = 0.f, a01 = 0.f, a10 = 0.f, a11 = 0.f;
    for (int k0 = 0; k0 < 128; k0 += 32) {
        #pragma unroll
        for (int i = 0; i < 4; i++) {
            int idx = tid + i * 256;
            int ka = idx & 31, ma = idx >> 5;
            As[ka][ma] = Ww[(m0 + ma) * 128 + k0 + ka];
            int nb = idx & 31, kb = idx >> 5;
            Bs[kb][nb] = Bsrc[(k0 + kb) * 128 + nb];
        }
        __syncthreads();
        #pragma unroll
        for (int kk = 0; kk < 32; kk++) {
            float2 a = *(const float2*)&As[kk][ty * 2];
            float2 b = *(const float2*)&Bs[kk][tx * 2];
            a00 += a.x * b.x; a01 += a.x * b.y;
            a10 += a.y * b.x; a11 += a.y * b.y;
        }
        __syncthreads();
    }
    int m = m0 + ty * 2, n = n0p + tx * 2;
    Wbig[m * 384 + n]           = a00;
    Wbig[m * 384 + n + 1]       = a01;
    Wbig[(m + 1) * 384 + n]     = a10;
    Wbig[(m + 1) * 384 + n + 1] = a11;
}

// ---------------- SGEMM 32x64 tile, 256 thr, 2x4 micro (float out) ---------
__global__ void sgemm2x4_kernel(const float* __restrict__ A0, const float* __restrict__ B0,
                                const float* __restrict__ bias0, float* __restrict__ C0,
                                const float* __restrict__ A1, const float* __restrict__ B1,
                                const float* __restrict__ bias1, float* __restrict__ C1,
                                int K, int lda, int ldb, int ldc, int relu)
{
    __shared__ float As[32][34];
    __shared__ float Bs[32][68];
    int z = blockIdx.z;
    bool use1 = (z == 1) && (C1 != 0);
    const float* A = use1 ? A1 : A0;
    const float* B = use1 ? B1 : B0;
    const float* bias = use1 ? bias1 : bias0;
    float* C = use1 ? C1 : C0;
    int m0 = blockIdx.y * 32, n0 = blockIdx.x * 64;
    int tid = threadIdx.x;
    int tx = tid & 15, ty = tid >> 4;
    float acc[2][4] = {};

    for (int k0 = 0; k0 < K; k0 += 32) {
        #pragma unroll
        for (int i = 0; i < 4; i++) {
            int idx = tid + i * 256;
            int ka = idx & 31, ma = idx >> 5;
            As[ka][ma] = A[(long)(m0 + ma) * lda + k0 + ka];
        }
        #pragma unroll
        for (int i = 0; i < 8; i++) {
            int idx = tid + i * 256;
            int nb = idx & 63, kb = idx >> 6;
            Bs[kb][nb] = B[(long)(k0 + kb) * ldb + n0 + nb];
        }
        __syncthreads();
        #pragma unroll
        for (int kk = 0; kk < 32; kk++) {
            float2 a = *(const float2*)&As[kk][ty * 2];
            float4 b = *(const float4*)&Bs[kk][tx * 4];
            float bv[4] = {b.x, b.y, b.z, b.w};
            #pragma unroll
            for (int j = 0; j < 4; j++) {
                acc[0][j] += a.x * bv[j];
                acc[1][j] += a.y * bv[j];
            }
        }
        __syncthreads();
    }
    int m = m0 + ty * 2, n = n0 + tx * 4;
    float bb[4] = {0.f, 0.f, 0.f, 0.f};
    if (bias) {
        #pragma unroll
        for (int j = 0; j < 4; j++) bb[j] = bias[n + j];
    }
    #pragma unroll
    for (int i = 0; i < 2; i++) {
        float4 o4;
        float v0 = acc[i][0] + bb[0], v1 = acc[i][1] + bb[1];
        float v2 = acc[i][2] + bb[2], v3 = acc[i][3] + bb[3];
        if (relu) { v0=fmaxf(v0,0.f); v1=fmaxf(v1,0.f); v2=fmaxf(v2,0.f); v3=fmaxf(v3,0.f); }
        o4.x=v0; o4.y=v1; o4.z=v2; o4.w=v3;
        *(float4*)&C[(long)(m + i) * ldc + n] = o4;
    }
}

// ---------------- FFN1: o2[1024x128] @ Wf1[128x512] + bf1, relu, fp16 out --
__global__ void ffn1_kernel(const float* __restrict__ A, const float* __restrict__ B,
                            const float* __restrict__ bias, __half* __restrict__ C)
{
    __shared__ float As[32][34];
    __shared__ float Bs[32][68];
    int m0 = blockIdx.y * 32, n0 = blockIdx.x * 64;
    int tid = threadIdx.x;
    int tx = tid & 15, ty = tid >> 4;
    float acc[2][4] = {};

    for (int k0 = 0; k0 < 128; k0 += 32) {
        #pragma unroll
        for (int i = 0; i < 4; i++) {
            int idx = tid + i * 256;
            int ka = idx & 31, ma = idx >> 5;
            As[ka][ma] = A[(long)(m0 + ma) * 128 + k0 + ka];
        }
        #pragma unroll
        for (int i = 0; i < 8; i++) {
            int idx = tid + i * 256;
            int nb = idx & 63, kb = idx >> 6;
            Bs[kb][nb] = B[(long)(k0 + kb) * 512 + n0 + nb];
        }
        __syncthreads();
        #pragma unroll
        for (int kk = 0; kk < 32; kk++) {
            float2 a = *(const float2*)&As[kk][ty * 2];
            float4 b = *(const float4*)&Bs[kk][tx * 4];
            float bv[4] = {b.x, b.y, b.z, b.w};
            #pragma unroll
            for (int j = 0; j < 4; j++) {
                acc[0][j] += a.x * bv[j];
                acc[1][j] += a.y * bv[j];
            }
        }
        __syncthreads();
    }
    int m = m0 + ty * 2, n = n0 + tx * 4;
    float4 b4 = *(const float4*)&bias[n];
    float bb[4] = {b4.x, b4.y, b4.z, b4.w};
    #pragma unroll
    for (int i = 0; i < 2; i++) {
        float v0 = fmaxf(acc[i][0] + bb[0], 0.f);
        float v1 = fmaxf(acc[i][1] + bb[1], 0.f);
        float v2 = fmaxf(acc[i][2] + bb[2], 0.f);
        float v3 = fmaxf(acc[i][3] + bb[3], 0.f);
        __half2 h01 = __floats2half2_rn(v0, v1);
        __half2 h23 = __floats2half2_rn(v2, v3);
        uint2 u;
        u.x = *(unsigned int*)&h01;
        u.y = *(unsigned int*)&h23;
        *(uint2*)&C[(long)(m + i) * 512 + n] = u;
    }
}

// ---------------- pairwise similarity; fp16 logit partials -----------------
__global__ void sim_kernel(const float* __restrict__ qbase, int ldq,
                           const float* __restrict__ kbase, int ldk,
                           const float* __restrict__ W2,
                           __half* __restrict__ lg, __half* __restrict__ lgT, int dual)
{
    __shared__ float sqa[32][34];
    __shared__ float sqb[32][34];
    __shared__ float skb[32][68];
    __shared__ float ska[32][68];
    __shared__ float sw[32];

    int z = blockIdx.z, b = z >> 2, hq = z & 3;
    int h0 = hq * 32;
    int q0 = blockIdx.y * 32, k0 = blockIdx.x * 64;
    const float* qp = qbase + (long)(b * SEQ + q0) * ldq;
    const float* kp = kbase + (long)(b * SEQ + k0) * ldk;
    int tid = threadIdx.x;
    int tx = tid & 15, ty = tid >> 4;
    float acc[2][4] = {};

    #pragma unroll
    for (int i = 0; i < 4; i++) {
        int idx = tid + i * 256;
        int r = idx >> 5, h = idx & 31;
        sqa[h][r] = qp[(long)r * ldq + h0 + h];
        if (dual) sqb[h][r] = qp[(long)r * ldq + 128 + h0 + h];
    }
    #pragma unroll
    for (int i = 0; i < 8; i++) {
        int idx = tid + i * 256;
        int r = idx >> 5, h = idx & 31;
        skb[h][r] = kp[(long)r * ldk + 128 + h0 + h];
        if (dual) ska[h][r] = kp[(long)r * ldk + h0 + h];
    }
    if (tid < 32) sw[tid] = W2[h0 + tid];
    __syncthreads();

    #pragma unroll 4
    for (int h = 0; h < 32; h++) {
        float w = sw[h];
        float2 a1r = *(const float2*)&sqa[h][ty * 2];
        float4 b1r = *(const float4*)&skb[h][tx * 4];
        float a1v[2] = {a1r.x, a1r.y};
        float b1v[4] = {b1r.x, b1r.y, b1r.z, b1r.w};
        #pragma unroll
        for (int i = 0; i < 2; i++)
            #pragma unroll
            for (int j = 0; j < 4; j++)
                acc[i][j] += fmaxf(a1v[i] + b1v[j], 0.f) * w;
        if (dual) {
            float2 qb = *(const float2*)&sqb[h][ty * 2];
            float4 ka = *(const float4*)&ska[h][tx * 4];
            float qv[2] = {qb.x, qb.y};
            float kv[4] = {ka.x, ka.y, ka.z, ka.w};
            #pragma unroll
            for (int i = 0; i < 2; i++)
                #pragma unroll
                for (int j = 0; j < 4; j++)
                    acc[i][j] += fmaxf(kv[j] + qv[i], 0.f) * w;
        }
    }

    __half* outp = lg + (long)hq * LGSZ;
    #pragma unroll
    for (int i = 0; i < 2; i++) {
        int q = q0 + ty * 2 + i;
        __half2 h01 = __floats2half2_rn(acc[i][0], acc[i][1]);
        __half2 h23 = __floats2half2_rn(acc[i][2], acc[i][3]);
        uint2 u;
        u.x = *(unsigned int*)&h01;
        u.y = *(unsigned int*)&h23;
        *(uint2*)&outp[((long)b * SEQ + q) * SEQ + k0 + tx * 4] = u;
    }

    if (!dual) {
        __syncthreads();
        float* st = &skb[0][0];
        #pragma unroll
        for (int i = 0; i < 2; i++) {
            int ql = ty * 2 + i;
            #pragma unroll
            for (int j = 0; j < 4; j++) {
                int kl = tx * 4 + j;
                st[kl * 33 + ql] = acc[i][j];
            }
        }
        __syncthreads();
        __half* outT = lgT + (long)hq * LGSZ;
        #pragma unroll
        for (int i = 0; i < 8; i++) {
            int idx = tid + i * 256;
            int r = idx >> 5, c = idx & 31;
            outT[((long)b * SEQ + k0 + r) * SEQ + q0 + c] = __float2half(st[r * 33 + c]);
        }
    }
}

// ---------------- fused softmax + (probs @ VW) + bias + residual + LN ------
// (R14-proven, cleaned)
__global__ void attn_ln_kernel(const __half* __restrict__ lg, const __half* __restrict__ lgT,
                               const float* __restrict__ mask, const float* __restrict__ b2p,
                               const float* __restrict__ VW, int ldvw,
                               const float* __restrict__ bias, const float* __restrict__ res,
                               const float* __restrict__ g, const float* __restrict__ be,
                               float* __restrict__ out, int sym)
{
    __shared__ float sprob[8][264];
    __shared__ float Bs[2][32][132];
    __shared__ float sacc[2][8][128];
    __shared__ float red[8][2][2];
    int m0 = blockIdx.x * 8;
    int b = m0 >> 8;
    int tid = threadIdx.x;
    int w = tid >> 5, lane = tid & 31;
    float c2 = 2.f * b2p[0];

    // ---- phase 1: softmax; warp pair per row ----
    {
        int r8 = w >> 1, hf = w & 1;
        int q = m0 + r8;
        long base4 = (long)q * SEQ + hf * 128 + lane * 4;
        float xs0 = 0.f, xs1 = 0.f, xs2 = 0.f, xs3 = 0.f;
        #pragma unroll
        for (int p = 0; p < 4; p++) {
            uint2 u = *(const uint2*)&lg[(long)p * LGSZ + base4];
            float2 f0 = __half22float2(*(__half2*)&u.x);
            float2 f1 = __half22float2(*(__half2*)&u.y);
            xs0 += f0.x; xs1 += f0.y; xs2 += f1.x; xs3 += f1.y;
        }
        if (sym) {
            #pragma unroll
            for (int p = 0; p < 4; p++) {
                uint2 u = *(const uint2*)&lgT[(long)p * LGSZ + base4];
                float2 f0 = __half22float2(*(__half2*)&u.x);
                float2 f1 = __half22float2(*(__half2*)&u.y);
                xs0 += f0.x; xs1 += f0.y; xs2 += f1.x; xs3 += f1.y;
            }
        }
        float4 mk = *(const float4*)&mask[base4];
        float xv[4];
        xv[0] = xs0 + c2 + mk.x * (-1e9f);
        xv[1] = xs1 + c2 + mk.y * (-1e9f);
        xv[2] = xs2 + c2 + mk.z * (-1e9f);
        xv[3] = xs3 + c2 + mk.w * (-1e9f);

        float mx = fmaxf(fmaxf(xv[0], xv[1]), fmaxf(xv[2], xv[3]));
        #pragma unroll
        for (int o = 16; o; o >>= 1) mx = fmaxf(mx, __shfl_xor_sync(0xffffffffu, mx, o));
        if (lane == 0) red[r8][hf][0] = mx;
        __syncthreads();
        float gmx = fmaxf(red[r8][0][0], red[r8][1][0]);
        float e0 = __expf(xv[0] - gmx), e1 = __expf(xv[1] - gmx);
        float e2 = __expf(xv[2] - gmx), e3 = __expf(xv[3] - gmx);
        float ssum = e0 + e1 + e2 + e3;
        float4 ev = {e0, e1, e2, e3};
        *(float4*)&sprob[r8][hf * 128 + lane * 4] = ev;
        #pragma unroll
        for (int o = 16; o; o >>= 1) ssum += __shfl_xor_sync(0xffffffffu, ssum, o);
        if (lane == 0) red[r8][hf][1] = ssum;
    }

    // ---- phase 2: warp = (kh, rq, cg): rows rq*4..+3, col cg*32+lane ----
    int kh = w >> 3, sub = w & 7;
    int rq = sub >> 2, cg = sub & 3;
    int n = cg * 32 + lane;
    float acc[4] = {};

    #pragma unroll
    for (int it = 0; it < 4; it++) {
        __syncthreads();
        #pragma unroll
        for (int j = 0; j < 2; j++) {
            int idx = tid + j * 512;
            int n4 = idx & 31, kb = idx >> 5;
            *(float4*)&Bs[0][kb][n4 * 4] =
                *(const float4*)&VW[(long)(b * SEQ + it * 32 + kb) * ldvw + n4 * 4];
            *(float4*)&Bs[1][kb][n4 * 4] =
                *(const float4*)&VW[(long)(b * SEQ + 128 + it * 32 + kb) * ldvw + n4 * 4];
        }
        __syncthreads();
        int kbase = kh * 128 + it * 32;
        #pragma unroll
        for (int kk = 0; kk < 32; kk++) {
            float bv = Bs[kh][kk][n];
            #pragma unroll
            for (int j = 0; j < 4; j++)
                acc[j] += sprob[rq * 4 + j][kbase + kk] * bv;
        }
    }

    #pragma unroll
    for (int j = 0; j < 4; j++)
        sacc[kh][rq * 4 + j][n] = acc[j];
    __syncthreads();

    // ---- epilogue: warp per row (tid < 256), 4 cols per lane, LN ----------
    if (tid < 256) {
        int r = tid >> 5;
        int q = m0 + r;
        float inv = 1.f / (red[r][0][1] + red[r][1][1]);
        float v[4];
        #pragma unroll
        for (int c = 0; c < 4; c++) {
            int nn = lane * 4 + c;
            v[c] = (sacc[0][r][nn] + sacc[1][r][nn]) * inv
                 + bias[nn] + res[(long)q * 128 + nn];
        }
        float s = v[0] + v[1] + v[2] + v[3];
        #pragma unroll
        for (int o = 16; o; o >>= 1) s += __shfl_xor_sync(0xffffffffu, s, o);
        float mean = s * (1.f / 128.f);
        float vs = 0.f;
        #pragma unroll
        for (int c = 0; c < 4; c++) { float d = v[c] - mean; vs += d * d; }
        #pragma unroll
        for (int o = 16; o; o >>= 1) vs += __shfl_xor_sync(0xffffffffu, vs, o);
        float invstd = rsqrtf(vs * (1.f / 128.f) + 1e-6f);
        #pragma unroll
        for (int c = 0; c < 4; c++) {
            int nn = lane * 4 + c;
            out[(long)q * 128 + nn] = (v[c] - mean) * invstd * g[nn] + be[nn];
        }
    }
}

// ---------------- FFN tail: LN(fh(fp16) @ Wf2 + bf2 + res), K=512 ----------
// 8 rows/block, 512 threads, grid 128; warp pair per row; 64-k chunks.
__global__ void gemm_ln_kernel(const __half* __restrict__ A,
                               const float* __restrict__ B,
                               const float* __restrict__ bias, const float* __restrict__ res,
                               const float* __restrict__ g, const float* __restrict__ be,
                               float* __restrict__ out)
{
    __shared__ float As[64][8];
    __shared__ float Bs[64][132];
    __shared__ float red[8][2][2];
    int m0 = blockIdx.x * 8;
    int tid = threadIdx.x;
    int w = tid >> 5, lane = tid & 31;
    int r8 = w >> 1, hf = w & 1;
    int q = m0 + r8;
    int n = hf * 64 + lane * 2;
    float acc0 = 0.f, acc1 = 0.f;

    for (int kc = 0; kc < 8; kc++) {
        if (kc) __syncthreads();
        #pragma unroll
        for (int i = 0; i < 4; i++) {              // B: 64k x 128n
            int idx = tid + i * 512;               // 0..2047 float4 units
            int n4 = idx & 31, kr = idx >> 5;
            *(float4*)&Bs[kr][n4 * 4] =
                *(const float4*)&B[(long)(kc * 64 + kr) * 128 + n4 * 4];
        }
        if (tid < 256) {                           // A: 8 rows x 64k (half2)
            int r = tid >> 5, c = tid & 31;
            __half2 h = *(const __half2*)&A[(long)(m0 + r) * 512 + kc * 64 + c * 2];
            float2 f = __half22float2(h);
            As[c * 2][r]     = f.x;
            As[c * 2 + 1][r] = f.y;
        }
        __syncthreads();
        #pragma unroll
        for (int kk = 0; kk < 64; kk++) {
            float a = As[kk][r8];
            float2 bv = *(const float2*)&Bs[kk][n];
            acc0 += a * bv.x;
            acc1 += a * bv.y;
        }
    }

    float v0 = acc0 + bias[n]     + res[(long)q * 128 + n];
    float v1 = acc1 + bias[n + 1] + res[(long)q * 128 + n + 1];
    float s = v0 + v1;
    #pragma unroll
    for (int o = 16; o; o >>= 1) s += __shfl_xor_sync(0xffffffffu, s, o);
    if (lane == 0) red[r8][hf][0] = s;
    __syncthreads();
    float mean = (red[r8][0][0] + red[r8][1][0]) * (1.f / 128.f);
    float d0 = v0 - mean, d1 = v1 - mean;
    float vs = d0 * d0 + d1 * d1;
    #pragma unroll
    for (int o = 16; o; o >>= 1) vs += __shfl_xor_sync(0xffffffffu, vs, o);
    if (lane == 0) red[r8][hf][1] = vs;
    __syncthreads();
    float invstd = rsqrtf((red[r8][0][1] + red[r8][1][1]) * (1.f / 128.f) + 1e-6f);
    out[(long)q * 128 + n]     = d0 * invstd * g[n]     + be[n];
    out[(long)q * 128 + n + 1] = d1 * invstd * g[n + 1] + be[n + 1];
}

// ---------------- host orchestration ----------------
extern "C" void kernel_launch(void* const* d_in, const int* in_sizes, int n_in,
                              void* d_out, int out_size)
{
    (void)in_sizes; (void)n_in; (void)out_size;
    const float* x    = (const float*)d_in[0];
    const float* enc  = (const float*)d_in[1];
    const float* cmsk = (const float*)d_in[2];
    const float* dmsk = (const float*)d_in[3];
    const float* W1q  = (const float*)d_in[4];
    const float* W1k  = (const float*)d_in[5];
    const float* b1   = (const float*)d_in[6];
    const float* W2   = (const float*)d_in[7];
    const float* b2   = (const float*)d_in[8];
    const float* Ww1  = (const float*)d_in[9];
    const float* bw1  = (const float*)d_in[10];
    const float* Wd1  = (const float*)d_in[11];
    const float* bd1  = (const float*)d_in[12];
    const float* Ww2  = (const float*)d_in[13];
    const float* bw2  = (const float*)d_in[14];
    const float* Wd2  = (const float*)d_in[15];
    const float* bd2  = (const float*)d_in[16];
    const float* Wf1  = (const float*)d_in[17];
    const float* bf1  = (const float*)d_in[18];
    const float* Wf2  = (const float*)d_in[19];
    const float* bf2  = (const float*)d_in[20];
    const float* ln1g = (const float*)d_in[21];
    const float* ln1b = (const float*)d_in[22];
    const float* ln2g = (const float*)d_in[23];
    const float* ln2b = (const float*)d_in[24];
    const float* ln3g = (const float*)d_in[25];
    const float* ln3b = (const float*)d_in[26];
    float* out = (float*)d_out;

    float *Wb1, *Wb2, *bb1, *bb2, *buf1, *buf2, *Tq, *o1, *o2;
    __half *lg, *lgT, *fh;
    cudaGetSymbolAddress((void**)&Wb1,   g_Wbig1);
    cudaGetSymbolAddress((void**)&Wb2,   g_Wbig2);
    cudaGetSymbolAddress((void**)&bb1,   g_bbig1);
    cudaGetSymbolAddress((void**)&bb2,   g_bbig2);
    cudaGetSymbolAddress((void**)&buf1,  g_buf1);
    cudaGetSymbolAddress((void**)&buf2,  g_buf2);
    cudaGetSymbolAddress((void**)&Tq,    g_Tq);
    cudaGetSymbolAddress((void**)&lg,    g_lg);
    cudaGetSymbolAddress((void**)&lgT,   g_lgT);
    cudaGetSymbolAddress((void**)&o1,    g_o1);
    cudaGetSymbolAddress((void**)&o2,    g_o2);
    cudaGetSymbolAddress((void**)&fh,    g_fh);

    dim3 simGrid(SEQ / 64, SEQ / 32, BSZ * 4);   // 512 blocks

    // ---- prep (weights only): Wbig tiles + bias row ----
    prep_kernel<<<dim3(12, 5, 2), 256>>>(Ww1, Ww2, W1q, W1k, Wd1, Wd2,
                                         bw1, bw2, b1, Wb1, Wb2, bb1, bb2);

    // ---- batched projection: buf = [TA | TB | VW] for x and enc ----
    sgemm2x4_kernel<<<dim3(6, 32, 2), 256>>>(x, Wb1, bb1, buf1,
                                             enc, Wb2, bb2, buf2,
                                             128, 128, 384, 384, 0);

    // ---- self-attention: logits = S + S^T (lgT written coalesced by sim) --
    sim_kernel<<<simGrid, 256>>>(buf1, 384, buf1, 384, W2, lg, lgT, 0);
    attn_ln_kernel<<<MROWS / 8, 512>>>(lg, lgT, cmsk, b2, buf1 + 256, 384,
                                       bd1, x, ln1g, ln1b, o1, 1);

    // ---- cross-attention ----
    sgemm2x4_kernel<<<dim3(4, 32, 1), 256>>>(o1, Wb2, bb2, Tq,
                                             0, 0, 0, 0,
                                             128, 128, 384, 256, 0);
    sim_kernel<<<simGrid, 256>>>(Tq, 256, buf2, 384, W2, lg, lgT, 1);
    attn_ln_kernel<<<MROWS / 8, 512>>>(lg, lgT, dmsk, b2, buf2 + 256, 384,
                                       bd2, o1, ln2g, ln2b, o2, 0);

    // ---- FFN ----
    ffn1_kernel<<<dim3(8, 32), 256>>>(o2, Wf1, bf1, fh);
    gemm_ln_kernel<<<MROWS / 8, 512>>>(fh, Wf2, bf2, o2, ln3g, ln3b, out);
}

// round 17
// speedup vs baseline: 1.0923x; 1.0155x over previous
#include <cuda_runtime.h>
#include <cuda_fp16.h>

#define BSZ 4
#define SEQ 256
#define DIM 128
#define HID 128
#define DFF 512
#define MROWS (BSZ*SEQ)   // 1024
#define LGSZ (BSZ*SEQ*SEQ)

// ---------------- scratch (device globals; no allocations) ----------------
__device__ float g_Wbig1[DIM*384];    // [Ww1@W1q | Ww1@W1k | Ww1@Wd1]
__device__ float g_Wbig2[DIM*384];
__device__ float g_bbig1[384];        // [bw1@W1q+b1 | bw1@W1k | bw1@Wd1]
__device__ float g_bbig2[384];
__device__ float g_buf1[MROWS*384];   // [T1A | T1B | VW1]
__device__ float g_buf2[MROWS*384];   // [TkA | TkB | VW2]
__device__ float g_Tq  [MROWS*256];   // [TqA | TqB]
__device__ __half g_lg [4*LGSZ];      // sim partials (4 H-quarters), fp16
__device__ __half g_lgT[4*LGSZ];      // transposed partials (self-attn only)
__device__ float g_o1 [MROWS*DIM];
__device__ float g_o2 [MROWS*DIM];
__device__ float g_fh [MROWS*DFF];

// ---------------- prep: Wbig tiles (y<4) + bbig (y==4), both sets (z) ------
__global__ void prep_kernel(const float* __restrict__ Ww1, const float* __restrict__ Ww2,
                            const float* __restrict__ W1q, const float* __restrict__ W1k,
                            const float* __restrict__ Wd1, const float* __restrict__ Wd2,
                            const float* __restrict__ bw1, const float* __restrict__ bw2,
                            const float* __restrict__ b1,
                            float* __restrict__ Wbig1, float* __restrict__ Wbig2,
                            float* __restrict__ bbig1, float* __restrict__ bbig2)
{
    const float* Ww = blockIdx.z ? Ww2 : Ww1;
    const float* Wd = blockIdx.z ? Wd2 : Wd1;
    const float* bw = blockIdx.z ? bw2 : bw1;
    float* Wbig = blockIdx.z ? Wbig2 : Wbig1;
    float* bbig = blockIdx.z ? bbig2 : bbig1;
    int n0p = blockIdx.x * 32;             // 0..352
    int grp = n0p >> 7;                    // 0:W1q 1:W1k 2:Wd
    const float* Bsrc = ((grp == 0) ? W1q : (grp == 1) ? W1k : Wd) + (n0p & 127);
    int tid = threadIdx.x;

    if (blockIdx.y == 4) {                 // bias row: bbig[n0p .. n0p+32)
        int w = tid >> 5, lane = tid & 31;
        for (int c = w; c < 32; c += 8) {
            int np = n0p + c;
            float s = 0.f;
            #pragma unroll
            for (int i = 0; i < 4; i++) {
                int k = lane + 32 * i;
                s += bw[k] * Bsrc[k * 128 + c];
            }
            #pragma unroll
            for (int o = 16; o; o >>= 1) s += __shfl_xor_sync(0xffffffffu, s, o);
            if (lane == 0) {
                if (grp == 0) s += b1[np & 127];
                bbig[np] = s;
            }
        }
        return;
    }

    int m0 = blockIdx.y * 32;
    __shared__ float As[32][34], Bs[32][34];
    int tx = tid & 15, ty = tid >> 4;
    float a00 = 0.f, a01 = 0.f, a10 = 0.f, a11 = 0.f;
    for (int k0 = 0; k0 < 128; k0 += 32) {
        #pragma unroll
        for (int i = 0; i < 4; i++) {
            int idx = tid + i * 256;
            int ka = idx & 31, ma = idx >> 5;
            As[ka][ma] = Ww[(m0 + ma) * 128 + k0 + ka];
            int nb = idx & 31, kb = idx >> 5;
            Bs[kb][nb] = Bsrc[(k0 + kb) * 128 + nb];
        }
        __syncthreads();
        #pragma unroll
        for (int kk = 0; kk < 32; kk++) {
            float2 a = *(const float2*)&As[kk][ty * 2];
            float2 b = *(const float2*)&Bs[kk][tx * 2];
            a00 += a.x * b.x; a01 += a.x * b.y;
            a10 += a.y * b.x; a11 += a.y * b.y;
        }
        __syncthreads();
    }
    int m = m0 + ty * 2, n = n0p + tx * 2;
    Wbig[m * 384 + n]           = a00;
    Wbig[m * 384 + n + 1]       = a01;
    Wbig[(m + 1) * 384 + n]     = a10;
    Wbig[(m + 1) * 384 + n + 1] = a11;
}

// ---------------- SGEMM 32x64 tile, 256 thr, 2x4 micro ---------------------
__global__ void sgemm2x4_kernel(const float* __restrict__ A0, const float* __restrict__ B0,
                                const float* __restrict__ bias0, float* __restrict__ C0,
                                const float* __restrict__ A1, const float* __restrict__ B1,
                                const float* __restrict__ bias1, float* __restrict__ C1,
                                int K, int lda, int ldb, int ldc, int relu)
{
    __shared__ float As[32][34];
    __shared__ float Bs[32][68];
    int z = blockIdx.z;
    bool use1 = (z == 1) && (C1 != 0);
    const float* A = use1 ? A1 : A0;
    const float* B = use1 ? B1 : B0;
    const float* bias = use1 ? bias1 : bias0;
    float* C = use1 ? C1 : C0;
    int m0 = blockIdx.y * 32, n0 = blockIdx.x * 64;
    int tid = threadIdx.x;
    int tx = tid & 15, ty = tid >> 4;
    float acc[2][4] = {};

    for (int k0 = 0; k0 < K; k0 += 32) {
        #pragma unroll
        for (int i = 0; i < 4; i++) {
            int idx = tid + i * 256;
            int ka = idx & 31, ma = idx >> 5;
            As[ka][ma] = A[(long)(m0 + ma) * lda + k0 + ka];
        }
        #pragma unroll
        for (int i = 0; i < 8; i++) {
            int idx = tid + i * 256;
            int nb = idx & 63, kb = idx >> 6;
            Bs[kb][nb] = B[(long)(k0 + kb) * ldb + n0 + nb];
        }
        __syncthreads();
        #pragma unroll
        for (int kk = 0; kk < 32; kk++) {
            float2 a = *(const float2*)&As[kk][ty * 2];
            float4 b = *(const float4*)&Bs[kk][tx * 4];
            float bv[4] = {b.x, b.y, b.z, b.w};
            #pragma unroll
            for (int j = 0; j < 4; j++) {
                acc[0][j] += a.x * bv[j];
                acc[1][j] += a.y * bv[j];
            }
        }
        __syncthreads();
    }
    int m = m0 + ty * 2, n = n0 + tx * 4;
    float bb[4] = {0.f, 0.f, 0.f, 0.f};
    if (bias) {
        #pragma unroll
        for (int j = 0; j < 4; j++) bb[j] = bias[n + j];
    }
    #pragma unroll
    for (int i = 0; i < 2; i++) {
        float4 o4;
        float v0 = acc[i][0] + bb[0], v1 = acc[i][1] + bb[1];
        float v2 = acc[i][2] + bb[2], v3 = acc[i][3] + bb[3];
        if (relu) { v0=fmaxf(v0,0.f); v1=fmaxf(v1,0.f); v2=fmaxf(v2,0.f); v3=fmaxf(v3,0.f); }
        o4.x=v0; o4.y=v1; o4.z=v2; o4.w=v3;
        *(float4*)&C[(long)(m + i) * ldc + n] = o4;
    }
}

// ---------------- pairwise similarity; fp16 logit partials -----------------
__global__ void sim_kernel(const float* __restrict__ qbase, int ldq,
                           const float* __restrict__ kbase, int ldk,
                           const float* __restrict__ W2,
                           __half* __restrict__ lg, __half* __restrict__ lgT, int dual)
{
    __shared__ float sqa[32][34];
    __shared__ float sqb[32][34];
    __shared__ float skb[32][68];
    __shared__ float ska[32][68];
    __shared__ float sw[32];

    int z = blockIdx.z, b = z >> 2, hq = z & 3;
    int h0 = hq * 32;
    int q0 = blockIdx.y * 32, k0 = blockIdx.x * 64;
    const float* qp = qbase + (long)(b * SEQ + q0) * ldq;
    const float* kp = kbase + (long)(b * SEQ + k0) * ldk;
    int tid = threadIdx.x;
    int tx = tid & 15, ty = tid >> 4;
    float acc[2][4] = {};

    #pragma unroll
    for (int i = 0; i < 4; i++) {
        int idx = tid + i * 256;
        int r = idx >> 5, h = idx & 31;
        sqa[h][r] = qp[(long)r * ldq + h0 + h];
        if (dual) sqb[h][r] = qp[(long)r * ldq + 128 + h0 + h];
    }
    #pragma unroll
    for (int i = 0; i < 8; i++) {
        int idx = tid + i * 256;
        int r = idx >> 5, h = idx & 31;
        skb[h][r] = kp[(long)r * ldk + 128 + h0 + h];
        if (dual) ska[h][r] = kp[(long)r * ldk + h0 + h];
    }
    if (tid < 32) sw[tid] = W2[h0 + tid];
    __syncthreads();

    #pragma unroll 4
    for (int h = 0; h < 32; h++) {
        float w = sw[h];
        float2 a1r = *(const float2*)&sqa[h][ty * 2];
        float4 b1r = *(const float4*)&skb[h][tx * 4];
        float a1v[2] = {a1r.x, a1r.y};
        float b1v[4] = {b1r.x, b1r.y, b1r.z, b1r.w};
        #pragma unroll
        for (int i = 0; i < 2; i++)
            #pragma unroll
            for (int j = 0; j < 4; j++)
                acc[i][j] += fmaxf(a1v[i] + b1v[j], 0.f) * w;
        if (dual) {
            float2 qb = *(const float2*)&sqb[h][ty * 2];
            float4 ka = *(const float4*)&ska[h][tx * 4];
            float qv[2] = {qb.x, qb.y};
            float kv[4] = {ka.x, ka.y, ka.z, ka.w};
            #pragma unroll
            for (int i = 0; i < 2; i++)
                #pragma unroll
                for (int j = 0; j < 4; j++)
                    acc[i][j] += fmaxf(kv[j] + qv[i], 0.f) * w;
        }
    }

    __half* outp = lg + (long)hq * LGSZ;
    #pragma unroll
    for (int i = 0; i < 2; i++) {
        int q = q0 + ty * 2 + i;
        __half2 h01 = __floats2half2_rn(acc[i][0], acc[i][1]);
        __half2 h23 = __floats2half2_rn(acc[i][2], acc[i][3]);
        uint2 u;
        u.x = *(unsigned int*)&h01;
        u.y = *(unsigned int*)&h23;
        *(uint2*)&outp[((long)b * SEQ + q) * SEQ + k0 + tx * 4] = u;
    }

    if (!dual) {
        __syncthreads();
        float* st = &skb[0][0];
        #pragma unroll
        for (int i = 0; i < 2; i++) {
            int ql = ty * 2 + i;
            #pragma unroll
            for (int j = 0; j < 4; j++) {
                int kl = tx * 4 + j;
                st[kl * 33 + ql] = acc[i][j];
            }
        }
        __syncthreads();
        __half* outT = lgT + (long)hq * LGSZ;
        #pragma unroll
        for (int i = 0; i < 8; i++) {
            int idx = tid + i * 256;
            int r = idx >> 5, c = idx & 31;
            outT[((long)b * SEQ + k0 + r) * SEQ + q0 + c] = __float2half(st[r * 33 + c]);
        }
    }
}

// ---------------- fused softmax + (probs @ VW) + bias + residual + LN ------
// 8 q-rows/block, 512 threads, grid 128. Probabilities stored TRANSPOSED
// (sprobT[k][row], row-dim padded to 12 for float4 alignment) so phase-2
// reads 4 row-probs per k with ONE broadcast LDS.128 (was 4 scalar LDS).
__global__ void attn_ln_kernel(const __half* __restrict__ lg, const __half* __restrict__ lgT,
                               const float* __restrict__ mask, const float* __restrict__ b2p,
                               const float* __restrict__ VW, int ldvw,
                               const float* __restrict__ bias, const float* __restrict__ res,
                               const float* __restrict__ g, const float* __restrict__ be,
                               float* __restrict__ out, int sym)
{
    __shared__ float sprobT[256][12];
    __shared__ float Bs[2][32][132];
    __shared__ float sacc[2][8][128];
    __shared__ float red[8][2][2];
    int m0 = blockIdx.x * 8;
    int b = m0 >> 8;
    int tid = threadIdx.x;
    int w = tid >> 5, lane = tid & 31;
    float c2 = 2.f * b2p[0];

    // ---- phase 1: softmax; warp pair per row ----
    {
        int r8 = w >> 1, hf = w & 1;
        int q = m0 + r8;
        long base4 = (long)q * SEQ + hf * 128 + lane * 4;
        float xs0 = 0.f, xs1 = 0.f, xs2 = 0.f, xs3 = 0.f;
        #pragma unroll
        for (int p = 0; p < 4; p++) {
            uint2 u = *(const uint2*)&lg[(long)p * LGSZ + base4];
            float2 f0 = __half22float2(*(__half2*)&u.x);
            float2 f1 = __half22float2(*(__half2*)&u.y);
            xs0 += f0.x; xs1 += f0.y; xs2 += f1.x; xs3 += f1.y;
        }
        if (sym) {
            #pragma unroll
            for (int p = 0; p < 4; p++) {
                uint2 u = *(const uint2*)&lgT[(long)p * LGSZ + base4];
                float2 f0 = __half22float2(*(__half2*)&u.x);
                float2 f1 = __half22float2(*(__half2*)&u.y);
                xs0 += f0.x; xs1 += f0.y; xs2 += f1.x; xs3 += f1.y;
            }
        }
        float4 mk = *(const float4*)&mask[base4];
        float xv[4];
        xv[0] = xs0 + c2 + mk.x * (-1e9f);
        xv[1] = xs1 + c2 + mk.y * (-1e9f);
        xv[2] = xs2 + c2 + mk.z * (-1e9f);
        xv[3] = xs3 + c2 + mk.w * (-1e9f);

        float mx = fmaxf(fmaxf(xv[0], xv[1]), fmaxf(xv[2], xv[3]));
        #pragma unroll
        for (int o = 16; o; o >>= 1) mx = fmaxf(mx, __shfl_xor_sync(0xffffffffu, mx, o));
        if (lane == 0) red[r8][hf][0] = mx;
        __syncthreads();
        float gmx = fmaxf(red[r8][0][0], red[r8][1][0]);
        float ev[4];
        float ssum = 0.f;
        #pragma unroll
        for (int i = 0; i < 4; i++) {
            ev[i] = __expf(xv[i] - gmx);
            ssum += ev[i];
        }
        int kb = hf * 128 + lane * 4;
        #pragma unroll
        for (int i = 0; i < 4; i++)
            sprobT[kb + i][r8] = ev[i];
        #pragma unroll
        for (int o = 16; o; o >>= 1) ssum += __shfl_xor_sync(0xffffffffu, ssum, o);
        if (lane == 0) red[r8][hf][1] = ssum;
    }

    // ---- phase 2: warp = (kh, rq, cg): rows rq*4..+3, col cg*32+lane ----
    int kh = w >> 3, sub = w & 7;
    int rq = sub >> 2, cg = sub & 3;
    int n = cg * 32 + lane;
    float acc[4] = {};

    #pragma unroll
    for (int it = 0; it < 4; it++) {
        __syncthreads();
        #pragma unroll
        for (int j = 0; j < 2; j++) {
            int idx = tid + j * 512;
            int n4 = idx & 31, kb = idx >> 5;
            *(float4*)&Bs[0][kb][n4 * 4] =
                *(const float4*)&VW[(long)(b * SEQ + it * 32 + kb) * ldvw + n4 * 4];
            *(float4*)&Bs[1][kb][n4 * 4] =
                *(const float4*)&VW[(long)(b * SEQ + 128 + it * 32 + kb) * ldvw + n4 * 4];
        }
        __syncthreads();
        int kbase = kh * 128 + it * 32;
        #pragma unroll
        for (int kk = 0; kk < 32; kk++) {
            float4 p = *(const float4*)&sprobT[kbase + kk][rq * 4];
            float bv = Bs[kh][kk][n];
            acc[0] += p.x * bv;
            acc[1] += p.y * bv;
            acc[2] += p.z * bv;
            acc[3] += p.w * bv;
        }
    }

    #pragma unroll
    for (int j = 0; j < 4; j++)
        sacc[kh][rq * 4 + j][n] = acc[j];
    __syncthreads();

    // ---- epilogue: warp per row (tid < 256), 4 cols per lane, LN ----------
    if (tid < 256) {
        int r = tid >> 5;
        int q = m0 + r;
        float inv = 1.f / (red[r][0][1] + red[r][1][1]);
        float v[4];
        #pragma unroll
        for (int c = 0; c < 4; c++) {
            int nn = lane * 4 + c;
            v[c] = (sacc[0][r][nn] + sacc[1][r][nn]) * inv
                 + bias[nn] + res[(long)q * 128 + nn];
        }
        float s = v[0] + v[1] + v[2] + v[3];
        #pragma unroll
        for (int o = 16; o; o >>= 1) s += __shfl_xor_sync(0xffffffffu, s, o);
        float mean = s * (1.f / 128.f);
        float vs = 0.f;
        #pragma unroll
        for (int c = 0; c < 4; c++) { float d = v[c] - mean; vs += d * d; }
        #pragma unroll
        for (int o = 16; o; o >>= 1) vs += __shfl_xor_sync(0xffffffffu, vs, o);
        float invstd = rsqrtf(vs * (1.f / 128.f) + 1e-6f);
        #pragma unroll
        for (int c = 0; c < 4; c++) {
            int nn = lane * 4 + c;
            out[(long)q * 128 + nn] = (v[c] - mean) * invstd * g[nn] + be[nn];
        }
    }
}

// ---------------- fused GEMM + bias + residual + LayerNorm (FFN tail) ------
// 8 rows/block, 512 threads, grid 128; warp pair per row (R11/R14-proven).
__global__ void gemm_ln_kernel(const float* __restrict__ A, int lda,
                               const float* __restrict__ B, int ldb,
                               const float* __restrict__ bias, const float* __restrict__ res,
                               const float* __restrict__ g, const float* __restrict__ be,
                               float* __restrict__ out, int K)
{
    __shared__ float As[32][8];
    __shared__ float Bs[32][132];
    __shared__ float red[8][2][2];
    int m0 = blockIdx.x * 8;
    int tid = threadIdx.x;
    int w = tid >> 5, lane = tid & 31;
    int r8 = w >> 1, hf = w & 1;
    int q = m0 + r8;
    int n = hf * 64 + lane * 2;
    float acc0 = 0.f, acc1 = 0.f;

    float4 rv[2];
    float ra = 0.f;
    #pragma unroll
    for (int i = 0; i < 2; i++) {
        int idx = tid + i * 512;
        int n4 = idx & 31, kb = idx >> 5;
        rv[i] = *(const float4*)&B[(long)kb * ldb + n4 * 4];
    }
    if (tid < 256) ra = A[(long)(m0 + (tid >> 5)) * lda + (tid & 31)];

    for (int k0 = 0; ; k0 += 32) {
        #pragma unroll
        for (int i = 0; i < 2; i++) {
            int idx = tid + i * 512;
            int n4 = idx & 31, kb = idx >> 5;
            *(float4*)&Bs[kb][n4 * 4] = rv[i];
        }
        if (tid < 256) As[tid & 31][tid >> 5] = ra;
        __syncthreads();
        bool more = (k0 + 32 < K);
        if (more) {
            #pragma unroll
            for (int i = 0; i < 2; i++) {
                int idx = tid + i * 512;
                int n4 = idx & 31, kb = idx >> 5;
                rv[i] = *(const float4*)&B[(long)(k0 + 32 + kb) * ldb + n4 * 4];
            }
            if (tid < 256) ra = A[(long)(m0 + (tid >> 5)) * lda + k0 + 32 + (tid & 31)];
        }
        #pragma unroll
        for (int kk = 0; kk < 32; kk++) {
            float a = As[kk][r8];
            float2 bv = *(const float2*)&Bs[kk][n];
            acc0 += a * bv.x;
            acc1 += a * bv.y;
        }
        if (!more) break;
        __syncthreads();
    }

    float v0 = acc0 + bias[n]     + res[(long)q * 128 + n];
    float v1 = acc1 + bias[n + 1] + res[(long)q * 128 + n + 1];
    float s = v0 + v1;
    #pragma unroll
    for (int o = 16; o; o >>= 1) s += __shfl_xor_sync(0xffffffffu, s, o);
    if (lane == 0) red[r8][hf][0] = s;
    __syncthreads();
    float mean = (red[r8][0][0] + red[r8][1][0]) * (1.f / 128.f);
    float d0 = v0 - mean, d1 = v1 - mean;
    float vs = d0 * d0 + d1 * d1;
    #pragma unroll
    for (int o = 16; o; o >>= 1) vs += __shfl_xor_sync(0xffffffffu, vs, o);
    if (lane == 0) red[r8][hf][1] = vs;
    __syncthreads();
    float invstd = rsqrtf((red[r8][0][1] + red[r8][1][1]) * (1.f / 128.f) + 1e-6f);
    out[(long)q * 128 + n]     = d0 * invstd * g[n]     + be[n];
    out[(long)q * 128 + n + 1] = d1 * invstd * g[n + 1] + be[n + 1];
}

// ---------------- host orchestration ----------------
extern "C" void kernel_launch(void* const* d_in, const int* in_sizes, int n_in,
                              void* d_out, int out_size)
{
    (void)in_sizes; (void)n_in; (void)out_size;
    const float* x    = (const float*)d_in[0];
    const float* enc  = (const float*)d_in[1];
    const float* cmsk = (const float*)d_in[2];
    const float* dmsk = (const float*)d_in[3];
    const float* W1q  = (const float*)d_in[4];
    const float* W1k  = (const float*)d_in[5];
    const float* b1   = (const float*)d_in[6];
    const float* W2   = (const float*)d_in[7];
    const float* b2   = (const float*)d_in[8];
    const float* Ww1  = (const float*)d_in[9];
    const float* bw1  = (const float*)d_in[10];
    const float* Wd1  = (const float*)d_in[11];
    const float* bd1  = (const float*)d_in[12];
    const float* Ww2  = (const float*)d_in[13];
    const float* bw2  = (const float*)d_in[14];
    const float* Wd2  = (const float*)d_in[15];
    const float* bd2  = (const float*)d_in[16];
    const float* Wf1  = (const float*)d_in[17];
    const float* bf1  = (const float*)d_in[18];
    const float* Wf2  = (const float*)d_in[19];
    const float* bf2  = (const float*)d_in[20];
    const float* ln1g = (const float*)d_in[21];
    const float* ln1b = (const float*)d_in[22];
    const float* ln2g = (const float*)d_in[23];
    const float* ln2b = (const float*)d_in[24];
    const float* ln3g = (const float*)d_in[25];
    const float* ln3b = (const float*)d_in[26];
    float* out = (float*)d_out;

    float *Wb1, *Wb2, *bb1, *bb2, *buf1, *buf2, *Tq, *o1, *o2, *fh;
    __half *lg, *lgT;
    cudaGetSymbolAddress((void**)&Wb1,   g_Wbig1);
    cudaGetSymbolAddress((void**)&Wb2,   g_Wbig2);
    cudaGetSymbolAddress((void**)&bb1,   g_bbig1);
    cudaGetSymbolAddress((void**)&bb2,   g_bbig2);
    cudaGetSymbolAddress((void**)&buf1,  g_buf1);
    cudaGetSymbolAddress((void**)&buf2,  g_buf2);
    cudaGetSymbolAddress((void**)&Tq,    g_Tq);
    cudaGetSymbolAddress((void**)&lg,    g_lg);
    cudaGetSymbolAddress((void**)&lgT,   g_lgT);
    cudaGetSymbolAddress((void**)&o1,    g_o1);
    cudaGetSymbolAddress((void**)&o2,    g_o2);
    cudaGetSymbolAddress((void**)&fh,    g_fh);

    dim3 simGrid(SEQ / 64, SEQ / 32, BSZ * 4);   // 512 blocks

    // ---- prep (weights only): Wbig tiles + bias row ----
    prep_kernel<<<dim3(12, 5, 2), 256>>>(Ww1, Ww2, W1q, W1k, Wd1, Wd2,
                                         bw1, bw2, b1, Wb1, Wb2, bb1, bb2);

    // ---- batched projection: buf = [TA | TB | VW] for x and enc ----
    sgemm2x4_kernel<<<dim3(6, 32, 2), 256>>>(x, Wb1, bb1, buf1,
                                             enc, Wb2, bb2, buf2,
                                             128, 128, 384, 384, 0);

    // ---- self-attention: logits = S + S^T (lgT written coalesced by sim) --
    sim_kernel<<<simGrid, 256>>>(buf1, 384, buf1, 384, W2, lg, lgT, 0);
    attn_ln_kernel<<<MROWS / 8, 512>>>(lg, lgT, cmsk, b2, buf1 + 256, 384,
                                       bd1, x, ln1g, ln1b, o1, 1);

    // ---- cross-attention ----
    sgemm2x4_kernel<<<dim3(4, 32, 1), 256>>>(o1, Wb2, bb2, Tq,
                                             0, 0, 0, 0,
                                             128, 128, 384, 256, 0);
    sim_kernel<<<simGrid, 256>>>(Tq, 256, buf2, 384, W2, lg, lgT, 1);
    attn_ln_kernel<<<MROWS / 8, 512>>>(lg, lgT, dmsk, b2, buf2 + 256, 384,
                                       bd2, o1, ln2g, ln2b, o2, 0);

    // ---- FFN ----
    sgemm2x4_kernel<<<dim3(8, 32, 1), 256>>>(o2, Wf1, bf1, fh, 0, 0, 0, 0,
                                             128, 128, 512, 512, 1);
    gemm_ln_kernel<<<MROWS / 8, 512>>>(fh, 512, Wf2, 128,
                                       bf2, o2, ln3g, ln3b, out, 512);
}